// round 4
// baseline (speedup 1.0000x reference)
#include <cuda_runtime.h>

// Problem dims (fixed by reference): x is (B=64, C=128, T=10000) float32, row-major.
#define B_DIM 64
#define C_DIM 128
#define T_DIM 10000
#define T4    (T_DIM / 4)   // 2500 float4 per row

// Scratch for per-(batch,time) channel means: 64*10000 floats = 2.56 MB.
__device__ float g_mu[B_DIM * T_DIM];

// ---------------------------------------------------------------------------
// K1: mu[b,t] = mean over channels of x[b,:,t].
// One thread per 4 consecutive t (float4). Warp reads 128B contiguous per
// channel iteration -> fully coalesced. 128 iterations, 4 fp32 accumulators.
// ---------------------------------------------------------------------------
__global__ __launch_bounds__(256)
void mu_kernel(const float* __restrict__ x) {
    const int b  = blockIdx.y;
    const int i4 = blockIdx.x * blockDim.x + threadIdx.x;  // float4 index within row
    if (i4 >= T4) return;

    const float4* __restrict__ xp =
        reinterpret_cast<const float4*>(x + (size_t)b * C_DIM * T_DIM);

    float sx = 0.f, sy = 0.f, sz = 0.f, sw = 0.f;
#pragma unroll 8
    for (int c = 0; c < C_DIM; ++c) {
        float4 v = xp[(size_t)c * T4 + i4];
        sx += v.x; sy += v.y; sz += v.z; sw += v.w;
    }
    const float inv = 1.0f / (float)C_DIM;
    float4 m;
    m.x = sx * inv; m.y = sy * inv; m.z = sz * inv; m.w = sw * inv;
    reinterpret_cast<float4*>(g_mu)[(size_t)b * T4 + i4] = m;
}

// ---------------------------------------------------------------------------
// K2: one CTA per (b,c) row. Compute d = x - mu, stash in smem, block-reduce
// sum/sumsq over T, then write (d - mean) * inv_std. One HBM read of the row,
// one HBM write; mu comes from L2 (2.56 MB total, shared by 128 CTAs/batch).
// ---------------------------------------------------------------------------
__global__ __launch_bounds__(512)
void norm_kernel(const float* __restrict__ x, float* __restrict__ out) {
    __shared__ float4 sh[T4];              // 40000 B
    __shared__ float  red_s[16], red_s2[16];
    __shared__ float  s_mean, s_inv;

    const int row = blockIdx.x;            // 0 .. B*C-1
    const int b   = row >> 7;              // row / 128

    const float4* __restrict__ xp =
        reinterpret_cast<const float4*>(x + (size_t)row * T_DIM);
    const float4* __restrict__ mp =
        reinterpret_cast<const float4*>(g_mu) + (size_t)b * T4;

    float s = 0.f, s2 = 0.f;
    for (int i = threadIdx.x; i < T4; i += 512) {
        float4 xv = xp[i];
        float4 mv = mp[i];
        float4 d;
        d.x = xv.x - mv.x; d.y = xv.y - mv.y;
        d.z = xv.z - mv.z; d.w = xv.w - mv.w;
        sh[i] = d;
        s  += d.x + d.y + d.z + d.w;
        s2 += d.x * d.x + d.y * d.y + d.z * d.z + d.w * d.w;
    }

    // intra-warp reduce
#pragma unroll
    for (int o = 16; o > 0; o >>= 1) {
        s  += __shfl_down_sync(0xffffffffu, s,  o);
        s2 += __shfl_down_sync(0xffffffffu, s2, o);
    }
    const int wid = threadIdx.x >> 5;
    const int lid = threadIdx.x & 31;
    if (lid == 0) { red_s[wid] = s; red_s2[wid] = s2; }
    __syncthreads();

    // final reduce across 16 warps, done by warp 0
    if (threadIdx.x < 32) {
        float a  = (lid < 16) ? red_s[lid]  : 0.f;
        float a2 = (lid < 16) ? red_s2[lid] : 0.f;
#pragma unroll
        for (int o = 8; o > 0; o >>= 1) {
            a  += __shfl_down_sync(0xffffffffu, a,  o);
            a2 += __shfl_down_sync(0xffffffffu, a2, o);
        }
        if (lid == 0) {
            const float invT = 1.0f / (float)T_DIM;
            float mean = a * invT;
            float var  = a2 * invT - mean * mean;
            float sd   = sqrtf(fmaxf(var, 0.0f));
            if (sd == 0.0f) sd = 1.0f;
            s_mean = mean;
            s_inv  = 1.0f / sd;
        }
    }
    __syncthreads();

    const float mean = s_mean;
    const float invs = s_inv;
    float4* __restrict__ op = reinterpret_cast<float4*>(out + (size_t)row * T_DIM);
    for (int i = threadIdx.x; i < T4; i += 512) {
        float4 d = sh[i];
        float4 r;
        r.x = (d.x - mean) * invs; r.y = (d.y - mean) * invs;
        r.z = (d.z - mean) * invs; r.w = (d.w - mean) * invs;
        op[i] = r;
    }
}

extern "C" void kernel_launch(void* const* d_in, const int* in_sizes, int n_in,
                              void* d_out, int out_size) {
    (void)in_sizes; (void)n_in; (void)out_size;
    const float* x   = (const float*)d_in[0];
    float*       out = (float*)d_out;

    dim3 g1((T4 + 255) / 256, B_DIM);
    mu_kernel<<<g1, 256>>>(x);

    norm_kernel<<<B_DIM * C_DIM, 512>>>(x, out);
}

// round 5
// speedup vs baseline: 1.0438x; 1.0438x over previous
#include <cuda_runtime.h>

// x: (B=64, C=128, T=10000) float32, row-major.
#define B_DIM 64
#define C_DIM 128
#define T_DIM 10000
#define T4    2500              // float4 per (b,c) row
#define K2_THREADS 512
#define K2_ITERS   5            // ceil(2500/512)

// Per-(batch,time) channel means: 64*10000 floats = 2.56 MB (lives in L2 for K2).
__device__ float g_mu[B_DIM * T_DIM];

// ---------------------------------------------------------------------------
// K1: mu[b,t] = mean over channels. One thread per float4 of t.
// 128 loads with constant 40000B stride -> immediate-offset LDGs, unroll 16
// for deep MLP. __ldcs: x streamed (evict-first), re-read from HBM by K2 anyway.
// ---------------------------------------------------------------------------
__global__ __launch_bounds__(256, 4)
void mu_kernel(const float* __restrict__ x) {
    const int b  = blockIdx.y;
    const int i4 = blockIdx.x * 256 + threadIdx.x;
    if (i4 >= T4) return;

    const float4* __restrict__ xp =
        reinterpret_cast<const float4*>(x) + (size_t)b * C_DIM * T4 + i4;

    float sx = 0.f, sy = 0.f, sz = 0.f, sw = 0.f;
#pragma unroll 16
    for (int c = 0; c < C_DIM; ++c) {
        float4 v = __ldcs(xp + (size_t)c * T4);
        sx += v.x; sy += v.y; sz += v.z; sw += v.w;
    }
    const float inv = 1.0f / (float)C_DIM;
    float4 m;
    m.x = sx * inv; m.y = sy * inv; m.z = sz * inv; m.w = sw * inv;
    reinterpret_cast<float4*>(g_mu)[(size_t)b * T4 + i4] = m;
}

// ---------------------------------------------------------------------------
// K2: one CTA per (b,c) row. d = x - mu held entirely in REGISTERS across the
// block reduction (no smem stash -> no L1 round trip). All 10 loads per thread
// issued up front for max MLP. x via __ldcs (evict-first), mu via default load
// (stays in L2, 128x reuse per batch), out via __stcs.
// ---------------------------------------------------------------------------
__global__ __launch_bounds__(K2_THREADS, 2)
void norm_kernel(const float* __restrict__ x, float* __restrict__ out) {
    __shared__ float red_s[16], red_s2[16];
    __shared__ float s_mean, s_inv;

    const int row = blockIdx.x;            // 0 .. B*C-1
    const int b   = row >> 7;

    const float4* __restrict__ xp =
        reinterpret_cast<const float4*>(x) + (size_t)row * T4;
    const float4* __restrict__ mp =
        reinterpret_cast<const float4*>(g_mu) + (size_t)b * T4;

    // Front-load all loads (up to 10 in flight per thread).
    float4 xv[K2_ITERS], mv[K2_ITERS];
#pragma unroll
    for (int k = 0; k < K2_ITERS; ++k) {
        const int i = threadIdx.x + k * K2_THREADS;
        if (i < T4) {
            xv[k] = __ldcs(xp + i);
            mv[k] = mp[i];
        }
    }

    // d = x - mu (overwrite xv), accumulate sum / sumsq.
    float s = 0.f, s2 = 0.f;
#pragma unroll
    for (int k = 0; k < K2_ITERS; ++k) {
        const int i = threadIdx.x + k * K2_THREADS;
        if (i < T4) {
            xv[k].x -= mv[k].x; xv[k].y -= mv[k].y;
            xv[k].z -= mv[k].z; xv[k].w -= mv[k].w;
            s  += xv[k].x + xv[k].y + xv[k].z + xv[k].w;
            s2 += xv[k].x * xv[k].x + xv[k].y * xv[k].y
                + xv[k].z * xv[k].z + xv[k].w * xv[k].w;
        }
    }

    // Block reduction (d stays live in registers across the barrier).
#pragma unroll
    for (int o = 16; o > 0; o >>= 1) {
        s  += __shfl_down_sync(0xffffffffu, s,  o);
        s2 += __shfl_down_sync(0xffffffffu, s2, o);
    }
    const int wid = threadIdx.x >> 5;
    const int lid = threadIdx.x & 31;
    if (lid == 0) { red_s[wid] = s; red_s2[wid] = s2; }
    __syncthreads();

    if (threadIdx.x < 32) {
        float a  = (lid < 16) ? red_s[lid]  : 0.f;
        float a2 = (lid < 16) ? red_s2[lid] : 0.f;
#pragma unroll
        for (int o = 8; o > 0; o >>= 1) {
            a  += __shfl_down_sync(0xffffffffu, a,  o);
            a2 += __shfl_down_sync(0xffffffffu, a2, o);
        }
        if (lid == 0) {
            const float invT = 1.0f / (float)T_DIM;
            float mean = a * invT;
            float var  = a2 * invT - mean * mean;
            float sd   = sqrtf(fmaxf(var, 0.0f));
            if (sd == 0.0f) sd = 1.0f;
            s_mean = mean;
            s_inv  = 1.0f / sd;
        }
    }
    __syncthreads();

    const float mean = s_mean;
    const float invs = s_inv;
    float4* __restrict__ op = reinterpret_cast<float4*>(out) + (size_t)row * T4;
#pragma unroll
    for (int k = 0; k < K2_ITERS; ++k) {
        const int i = threadIdx.x + k * K2_THREADS;
        if (i < T4) {
            float4 r;
            r.x = (xv[k].x - mean) * invs;
            r.y = (xv[k].y - mean) * invs;
            r.z = (xv[k].z - mean) * invs;
            r.w = (xv[k].w - mean) * invs;
            __stcs(op + i, r);
        }
    }
}

extern "C" void kernel_launch(void* const* d_in, const int* in_sizes, int n_in,
                              void* d_out, int out_size) {
    (void)in_sizes; (void)n_in; (void)out_size;
    const float* x   = (const float*)d_in[0];
    float*       out = (float*)d_out;

    dim3 g1((T4 + 255) / 256, B_DIM);
    mu_kernel<<<g1, 256>>>(x);

    norm_kernel<<<B_DIM * C_DIM, K2_THREADS>>>(x, out);
}

// round 6
// speedup vs baseline: 1.0500x; 1.0060x over previous
#include <cuda_runtime.h>

// x: (B=64, C=128, T=10000) float32, row-major.
#define B_DIM 64
#define C_DIM 128
#define T_DIM 10000
#define T4    2500              // float4 per (b,c) row
#define K2_THREADS 512
#define K2_ITERS   5            // ceil(2500/512)

// Per-(batch,time) channel means: 64*10000 floats = 2.56 MB (lives in L2 for K2).
__device__ float g_mu[B_DIM * T_DIM];

// ---------------------------------------------------------------------------
// K1: mu[b,t] = mean over channels. One thread per float4 of t.
// 128 loads with constant 40000B stride -> immediate-offset LDGs, unroll 16
// for deep MLP. __ldcs: x streamed (evict-first), re-read from HBM by K2 anyway.
// ---------------------------------------------------------------------------
__global__ __launch_bounds__(256, 4)
void mu_kernel(const float* __restrict__ x) {
    const int b  = blockIdx.y;
    const int i4 = blockIdx.x * 256 + threadIdx.x;
    if (i4 >= T4) return;

    const float4* __restrict__ xp =
        reinterpret_cast<const float4*>(x) + (size_t)b * C_DIM * T4 + i4;

    float sx = 0.f, sy = 0.f, sz = 0.f, sw = 0.f;
#pragma unroll 16
    for (int c = 0; c < C_DIM; ++c) {
        float4 v = __ldcs(xp + (size_t)c * T4);
        sx += v.x; sy += v.y; sz += v.z; sw += v.w;
    }
    const float inv = 1.0f / (float)C_DIM;
    float4 m;
    m.x = sx * inv; m.y = sy * inv; m.z = sz * inv; m.w = sw * inv;
    reinterpret_cast<float4*>(g_mu)[(size_t)b * T4 + i4] = m;
}

// ---------------------------------------------------------------------------
// K2: one CTA per (b,c) row. d = x - mu held entirely in REGISTERS across the
// block reduction (no smem stash -> no L1 round trip). All 10 loads per thread
// issued up front for max MLP. x via __ldcs (evict-first), mu via default load
// (stays in L2, 128x reuse per batch), out via __stcs.
// ---------------------------------------------------------------------------
__global__ __launch_bounds__(K2_THREADS, 2)
void norm_kernel(const float* __restrict__ x, float* __restrict__ out) {
    __shared__ float red_s[16], red_s2[16];
    __shared__ float s_mean, s_inv;

    const int row = blockIdx.x;            // 0 .. B*C-1
    const int b   = row >> 7;

    const float4* __restrict__ xp =
        reinterpret_cast<const float4*>(x) + (size_t)row * T4;
    const float4* __restrict__ mp =
        reinterpret_cast<const float4*>(g_mu) + (size_t)b * T4;

    // Front-load all loads (up to 10 in flight per thread).
    float4 xv[K2_ITERS], mv[K2_ITERS];
#pragma unroll
    for (int k = 0; k < K2_ITERS; ++k) {
        const int i = threadIdx.x + k * K2_THREADS;
        if (i < T4) {
            xv[k] = __ldcs(xp + i);
            mv[k] = mp[i];
        }
    }

    // d = x - mu (overwrite xv), accumulate sum / sumsq.
    float s = 0.f, s2 = 0.f;
#pragma unroll
    for (int k = 0; k < K2_ITERS; ++k) {
        const int i = threadIdx.x + k * K2_THREADS;
        if (i < T4) {
            xv[k].x -= mv[k].x; xv[k].y -= mv[k].y;
            xv[k].z -= mv[k].z; xv[k].w -= mv[k].w;
            s  += xv[k].x + xv[k].y + xv[k].z + xv[k].w;
            s2 += xv[k].x * xv[k].x + xv[k].y * xv[k].y
                + xv[k].z * xv[k].z + xv[k].w * xv[k].w;
        }
    }

    // Block reduction (d stays live in registers across the barrier).
#pragma unroll
    for (int o = 16; o > 0; o >>= 1) {
        s  += __shfl_down_sync(0xffffffffu, s,  o);
        s2 += __shfl_down_sync(0xffffffffu, s2, o);
    }
    const int wid = threadIdx.x >> 5;
    const int lid = threadIdx.x & 31;
    if (lid == 0) { red_s[wid] = s; red_s2[wid] = s2; }
    __syncthreads();

    if (threadIdx.x < 32) {
        float a  = (lid < 16) ? red_s[lid]  : 0.f;
        float a2 = (lid < 16) ? red_s2[lid] : 0.f;
#pragma unroll
        for (int o = 8; o > 0; o >>= 1) {
            a  += __shfl_down_sync(0xffffffffu, a,  o);
            a2 += __shfl_down_sync(0xffffffffu, a2, o);
        }
        if (lid == 0) {
            const float invT = 1.0f / (float)T_DIM;
            float mean = a * invT;
            float var  = a2 * invT - mean * mean;
            float sd   = sqrtf(fmaxf(var, 0.0f));
            if (sd == 0.0f) sd = 1.0f;
            s_mean = mean;
            s_inv  = 1.0f / sd;
        }
    }
    __syncthreads();

    const float mean = s_mean;
    const float invs = s_inv;
    float4* __restrict__ op = reinterpret_cast<float4*>(out) + (size_t)row * T4;
#pragma unroll
    for (int k = 0; k < K2_ITERS; ++k) {
        const int i = threadIdx.x + k * K2_THREADS;
        if (i < T4) {
            float4 r;
            r.x = (xv[k].x - mean) * invs;
            r.y = (xv[k].y - mean) * invs;
            r.z = (xv[k].z - mean) * invs;
            r.w = (xv[k].w - mean) * invs;
            __stcs(op + i, r);
        }
    }
}

extern "C" void kernel_launch(void* const* d_in, const int* in_sizes, int n_in,
                              void* d_out, int out_size) {
    (void)in_sizes; (void)n_in; (void)out_size;
    const float* x   = (const float*)d_in[0];
    float*       out = (float*)d_out;

    dim3 g1((T4 + 255) / 256, B_DIM);
    mu_kernel<<<g1, 256>>>(x);

    norm_kernel<<<B_DIM * C_DIM, K2_THREADS>>>(x, out);
}